// round 2
// baseline (speedup 1.0000x reference)
#include <cuda_runtime.h>
#include <mma.h>
#include <cstdint>

using namespace nvcuda;

#define NN    512
#define EIN   128
#define HID   384
#define OUTD  128
#define TILE  64      // j-rows per CTA
#define NTHREADS 256

// ---- device scratch (allocation-free rule: __device__ globals) ----
__device__ float g_nb[NN * 128];          // node projection
__device__ float g_A0[NN * HID];          // nb@w_t0[128:256] + b_t0   (i-part, trunk0)
__device__ float g_B0[NN * HID];          // nb@w_t0[256:384]          (j-part, trunk0)
__device__ float g_Af[NN * OUTD];         // nb@w_fin[128:256] + b_fin (i-part, final)
__device__ float g_Bf[NN * OUTD];         // nb@w_fin[256:384]         (j-part, final)

__device__ __forceinline__ float tf32r(float x) {
    float y;
    asm("cvt.rna.tf32.f32 %0, %1;" : "=f"(y) : "f"(x));
    return y;
}

// ---------------- precompute 1: nb = node @ w_init + b_init ----------------
__global__ void k_nb(const float* __restrict__ node,
                     const float* __restrict__ w_init,
                     const float* __restrict__ b_init) {
    int i = blockIdx.x;
    int t = threadIdx.x;              // 128 threads
    __shared__ float sn[256];
    for (int c = t; c < 256; c += 128) sn[c] = node[i * 256 + c];
    __syncthreads();
    float acc = b_init[t];
#pragma unroll 8
    for (int k = 0; k < 256; k++) acc += sn[k] * w_init[k * 128 + t];
    g_nb[i * 128 + t] = acc;
}

// ---------------- precompute 2: per-node bias rows ----------------
__global__ void k_bias(const float* __restrict__ w_t0, const float* __restrict__ b_t0,
                       const float* __restrict__ w_fin, const float* __restrict__ b_fin) {
    int i = blockIdx.x;
    int t = threadIdx.x;              // 384 threads
    __shared__ float sn[128];
    if (t < 128) sn[t] = g_nb[i * 128 + t];
    __syncthreads();
    float a = b_t0[t], b2 = 0.f;
#pragma unroll 8
    for (int k = 0; k < 128; k++) {
        float nv = sn[k];
        a  += nv * w_t0[(128 + k) * HID + t];
        b2 += nv * w_t0[(256 + k) * HID + t];
    }
    g_A0[i * HID + t] = a;
    g_B0[i * HID + t] = b2;
    if (t < 128) {
        float af = b_fin[t], bf = 0.f;
#pragma unroll 8
        for (int k = 0; k < 128; k++) {
            float nv = sn[k];
            af += nv * w_fin[(128 + k) * OUTD + t];
            bf += nv * w_fin[(256 + k) * OUTD + t];
        }
        g_Af[i * OUTD + t] = af;
        g_Bf[i * OUTD + t] = bf;
    }
}

// ---------------- main fused kernel ----------------
// SMEM layout (floats):
static constexpr int LDE = 136;                   // E: 64 x 128 (pad)
static constexpr int LDU = 392;                   // U: 64 x 384 (pad)
static constexpr int LDV = 72;                    // V chunk: 64 x 64 (pad)
static constexpr int OFF_E  = 0;
static constexpr int OFF_U  = OFF_E + TILE * LDE;     // 8704
static constexpr int OFF_V  = OFF_U + TILE * LDU;     // 33792
static constexpr int OFF_W  = OFF_V + TILE * LDV;     // 38400
static constexpr int OFF_BA = OFF_W + 32 * 384;       // 50688 (panel max 12288 floats)
static constexpr int SMEM_FLOATS = OFF_BA + HID;      // 51072
static constexpr int SMEM_BYTES  = SMEM_FLOATS * 4;   // 204288 B

__device__ __forceinline__ void load_panel(float* __restrict__ sW,
                                           const float* __restrict__ W,
                                           int k0, int rows, int c0, int cols,
                                           int rstride, int tid) {
    int cpr = cols >> 2;
    int total = rows * cpr;
    for (int idx = tid; idx < total; idx += NTHREADS) {
        int r = idx / cpr, c4 = idx - r * cpr;
        float4 x = *(const float4*)(W + (size_t)(k0 + r) * rstride + c0 + (c4 << 2));
        x.x = tf32r(x.x); x.y = tf32r(x.y); x.z = tf32r(x.z); x.w = tf32r(x.w);
        *(float4*)(sW + r * cols + (c4 << 2)) = x;
    }
}

__global__ __launch_bounds__(NTHREADS, 1)
void k_main(const float* __restrict__ edge,
            const float* __restrict__ w_t0,
            const float* __restrict__ b_t1,
            const float* __restrict__ w_t1,
            const float* __restrict__ w_fin,
            const float* __restrict__ ln_g,
            const float* __restrict__ ln_b,
            float* __restrict__ out) {
    extern __shared__ float sm[];
    float* sE  = sm + OFF_E;
    float* sU  = sm + OFF_U;
    float* sV  = sm + OFF_V;
    float* sW  = sm + OFF_W;
    float* sBA = sm + OFF_BA;

    const int tid  = threadIdx.x;
    const int lane = tid & 31;
    const int wid  = tid >> 5;
    const int wy   = wid & 3;     // M tile (rows wy*16)
    const int wx   = wid >> 2;    // N split

    const int i  = blockIdx.x >> 3;
    const int j0 = (blockIdx.x & 7) * TILE;

    // ---- phase 0: load E tile (tf32-rounded) + A0 row ----
    {
        const float4* src = (const float4*)(edge + (size_t)(i * NN + j0) * EIN);
        for (int v = tid; v < TILE * 32; v += NTHREADS) {
            int r = v >> 5, c4 = v & 31;
            float4 x = src[r * 32 + c4];
            x.x = tf32r(x.x); x.y = tf32r(x.y); x.z = tf32r(x.z); x.w = tf32r(x.w);
            int o = r * LDE + (c4 << 2);
            sE[o] = x.x; sE[o + 1] = x.y; sE[o + 2] = x.z; sE[o + 3] = x.w;
        }
        for (int c = tid; c < HID; c += NTHREADS) sBA[c] = g_A0[i * HID + c];
    }

    // ---- GEMM-A: U = relu(E @ W0e + A0[i] + B0[j]) ; M=64 N=384 K=128 ----
    {
        wmma::fragment<wmma::accumulator, 16, 16, 8, float> acc[12];
#pragma unroll
        for (int n = 0; n < 12; n++) wmma::fill_fragment(acc[n], 0.f);
        for (int kc = 0; kc < EIN; kc += 32) {
            __syncthreads();
            load_panel(sW, w_t0, kc, 32, 0, 384, HID, tid);
            __syncthreads();
#pragma unroll
            for (int k8 = 0; k8 < 32; k8 += 8) {
                wmma::fragment<wmma::matrix_a, 16, 16, 8, wmma::precision::tf32, wmma::row_major> a;
                wmma::load_matrix_sync(a, sE + wy * 16 * LDE + kc + k8, LDE);
#pragma unroll
                for (int n = 0; n < 12; n++) {
                    wmma::fragment<wmma::matrix_b, 16, 16, 8, wmma::precision::tf32, wmma::row_major> b;
                    wmma::load_matrix_sync(b, sW + k8 * 384 + wx * 192 + n * 16, 384);
                    wmma::mma_sync(acc[n], a, b, acc[n]);
                }
            }
        }
        __syncthreads();
#pragma unroll
        for (int n = 0; n < 12; n++)
            wmma::store_matrix_sync(sU + wy * 16 * LDU + wx * 192 + n * 16, acc[n], LDU,
                                    wmma::mem_row_major);
        __syncthreads();
        // bias + relu + tf32-round
        for (int v = tid; v < TILE * HID; v += NTHREADS) {
            int r = v / HID, c = v - r * HID;
            float x = sU[r * LDU + c] + sBA[c] + g_B0[(size_t)(j0 + r) * HID + c];
            sU[r * LDU + c] = tf32r(fmaxf(x, 0.f));
        }
    }

    // ---- GEMM-B: O_acc = E @ w_fin[0:128,:] ; M=64 N=128 K=128 (regs persist) ----
    wmma::fragment<wmma::accumulator, 16, 16, 8, float> accO[4];
#pragma unroll
    for (int n = 0; n < 4; n++) wmma::fill_fragment(accO[n], 0.f);
    for (int kc = 0; kc < EIN; kc += 32) {
        __syncthreads();
        load_panel(sW, w_fin, kc, 32, 0, 128, OUTD, tid);
        __syncthreads();
#pragma unroll
        for (int k8 = 0; k8 < 32; k8 += 8) {
            wmma::fragment<wmma::matrix_a, 16, 16, 8, wmma::precision::tf32, wmma::row_major> a;
            wmma::load_matrix_sync(a, sE + wy * 16 * LDE + kc + k8, LDE);
#pragma unroll
            for (int n = 0; n < 4; n++) {
                wmma::fragment<wmma::matrix_b, 16, 16, 8, wmma::precision::tf32, wmma::row_major> b;
                wmma::load_matrix_sync(b, sW + k8 * 128 + wx * 64 + n * 16, 128);
                wmma::mma_sync(accO[n], a, b, accO[n]);
            }
        }
    }

    // ---- GEMM-C/D chunked: V = relu(U@W1[:,chunk]+b1); O_acc += V @ w_fin[chunk,:] ----
    for (int vc = 0; vc < 6; vc++) {
        wmma::fragment<wmma::accumulator, 16, 16, 8, float> accV[2];
        wmma::fill_fragment(accV[0], 0.f);
        wmma::fill_fragment(accV[1], 0.f);
        for (int kc = 0; kc < HID; kc += 64) {
            __syncthreads();
            load_panel(sW, w_t1, kc, 64, vc * 64, 64, HID, tid);
            __syncthreads();
#pragma unroll
            for (int k8 = 0; k8 < 64; k8 += 8) {
                wmma::fragment<wmma::matrix_a, 16, 16, 8, wmma::precision::tf32, wmma::row_major> a;
                wmma::load_matrix_sync(a, sU + wy * 16 * LDU + kc + k8, LDU);
#pragma unroll
                for (int s = 0; s < 2; s++) {
                    wmma::fragment<wmma::matrix_b, 16, 16, 8, wmma::precision::tf32, wmma::row_major> b;
                    wmma::load_matrix_sync(b, sW + k8 * 64 + wx * 32 + s * 16, 64);
                    wmma::mma_sync(accV[s], a, b, accV[s]);
                }
            }
        }
        __syncthreads();
#pragma unroll
        for (int s = 0; s < 2; s++)
            wmma::store_matrix_sync(sV + wy * 16 * LDV + wx * 32 + s * 16, accV[s], LDV,
                                    wmma::mem_row_major);
        __syncthreads();
        for (int v = tid; v < TILE * 64; v += NTHREADS) {
            int r = v >> 6, c = v & 63;
            float x = sV[r * LDV + c] + b_t1[vc * 64 + c];
            sV[r * LDV + c] = tf32r(fmaxf(x, 0.f));
        }
        __syncthreads();
        load_panel(sW, w_fin, vc * 64, 64, 0, 128, OUTD, tid);
        __syncthreads();
#pragma unroll
        for (int k8 = 0; k8 < 64; k8 += 8) {
            wmma::fragment<wmma::matrix_a, 16, 16, 8, wmma::precision::tf32, wmma::row_major> a;
            wmma::load_matrix_sync(a, sV + wy * 16 * LDV + k8, LDV);
#pragma unroll
            for (int n = 0; n < 4; n++) {
                wmma::fragment<wmma::matrix_b, 16, 16, 8, wmma::precision::tf32, wmma::row_major> b;
                wmma::load_matrix_sync(b, sW + k8 * 128 + wx * 64 + n * 16, 128);
                wmma::mma_sync(accO[n], a, b, accO[n]);
            }
        }
    }

    // ---- epilogue: O + Af[i] + Bf[j], LayerNorm, store ----
    float* sO = sU;  // reuse (64 x 136)
    __syncthreads();
#pragma unroll
    for (int n = 0; n < 4; n++)
        wmma::store_matrix_sync(sO + wy * 16 * 136 + wx * 64 + n * 16, accO[n], 136,
                                wmma::mem_row_major);
    __syncthreads();

    for (int rr = 0; rr < 8; rr++) {
        int r = wid * 8 + rr;
        float x[4];
        float sum = 0.f;
#pragma unroll
        for (int q = 0; q < 4; q++) {
            int c = lane + q * 32;
            x[q] = sO[r * 136 + c] + g_Af[i * OUTD + c] + g_Bf[(size_t)(j0 + r) * OUTD + c];
            sum += x[q];
        }
#pragma unroll
        for (int off = 16; off; off >>= 1) sum += __shfl_xor_sync(0xffffffffu, sum, off);
        float mu = sum * (1.f / 128.f);
        float vs = 0.f;
#pragma unroll
        for (int q = 0; q < 4; q++) { float d = x[q] - mu; vs += d * d; }
#pragma unroll
        for (int off = 16; off; off >>= 1) vs += __shfl_xor_sync(0xffffffffu, vs, off);
        float inv = rsqrtf(vs * (1.f / 128.f) + 1e-5f);
        size_t base = (size_t)(i * NN + j0 + r) * OUTD;
#pragma unroll
        for (int q = 0; q < 4; q++) {
            int c = lane + q * 32;
            out[base + c] = (x[q] - mu) * inv * ln_g[c] + ln_b[c];
        }
    }
}

extern "C" void kernel_launch(void* const* d_in, const int* in_sizes, int n_in,
                              void* d_out, int out_size) {
    const float* node   = (const float*)d_in[0];
    const float* edge   = (const float*)d_in[1];
    const float* w_init = (const float*)d_in[2];
    const float* b_init = (const float*)d_in[3];
    const float* w_t0   = (const float*)d_in[4];
    const float* b_t0   = (const float*)d_in[5];
    const float* w_t1   = (const float*)d_in[6];
    const float* b_t1   = (const float*)d_in[7];
    const float* w_fin  = (const float*)d_in[8];
    const float* b_fin  = (const float*)d_in[9];
    const float* ln_g   = (const float*)d_in[10];
    const float* ln_b   = (const float*)d_in[11];
    float* out = (float*)d_out;

    cudaFuncSetAttribute(k_main, cudaFuncAttributeMaxDynamicSharedMemorySize, SMEM_BYTES);

    k_nb<<<NN, 128>>>(node, w_init, b_init);
    k_bias<<<NN, 384>>>(w_t0, b_t0, w_fin, b_fin);
    k_main<<<NN * 8, NTHREADS, SMEM_BYTES>>>(edge, w_t0, b_t1, w_t1, w_fin, ln_g, ln_b, out);
}

// round 4
// speedup vs baseline: 1.7988x; 1.7988x over previous
#include <cuda_runtime.h>
#include <mma.h>
#include <cstdint>

using namespace nvcuda;

#define NN    512
#define EIN   128
#define HID   384
#define OUTD  128
#define TILE  64      // j-rows per CTA
#define NTHREADS 256

// ---- device scratch (allocation-free rule: __device__ globals) ----
__device__ float g_nb[NN * 128];          // node projection
__device__ float g_A0[NN * HID];          // nb@w_t0[128:256] + b_t0   (i-part, trunk0)
__device__ float g_B0[NN * HID];          // nb@w_t0[256:384]          (j-part, trunk0)
__device__ float g_Af[NN * OUTD];         // nb@w_fin[128:256] + b_fin (i-part, final)
__device__ float g_Bf[NN * OUTD];         // nb@w_fin[256:384]         (j-part, final)

__device__ __forceinline__ float tf32r(float x) {
    float y;
    asm("cvt.rna.tf32.f32 %0, %1;" : "=f"(y) : "f"(x));
    return y;
}

// ---------------- precompute 1: nb = node @ w_init + b_init ----------------
__global__ void k_nb(const float* __restrict__ node,
                     const float* __restrict__ w_init,
                     const float* __restrict__ b_init) {
    int i = blockIdx.x;
    int t = threadIdx.x;              // 128 threads
    __shared__ float sn[256];
    for (int c = t; c < 256; c += 128) sn[c] = node[i * 256 + c];
    __syncthreads();
    float acc = b_init[t];
#pragma unroll 8
    for (int k = 0; k < 256; k++) acc += sn[k] * w_init[k * 128 + t];
    g_nb[i * 128 + t] = acc;
}

// ---------------- precompute 2: per-node bias rows ----------------
__global__ void k_bias(const float* __restrict__ w_t0, const float* __restrict__ b_t0,
                       const float* __restrict__ w_fin, const float* __restrict__ b_fin) {
    int i = blockIdx.x;
    int t = threadIdx.x;              // 384 threads
    __shared__ float sn[128];
    if (t < 128) sn[t] = g_nb[i * 128 + t];
    __syncthreads();
    float a = b_t0[t], b2 = 0.f;
#pragma unroll 8
    for (int k = 0; k < 128; k++) {
        float nv = sn[k];
        a  += nv * w_t0[(128 + k) * HID + t];
        b2 += nv * w_t0[(256 + k) * HID + t];
    }
    g_A0[i * HID + t] = a;
    g_B0[i * HID + t] = b2;
    if (t < 128) {
        float af = b_fin[t], bf = 0.f;
#pragma unroll 8
        for (int k = 0; k < 128; k++) {
            float nv = sn[k];
            af += nv * w_fin[(128 + k) * OUTD + t];
            bf += nv * w_fin[(256 + k) * OUTD + t];
        }
        g_Af[i * OUTD + t] = af;
        g_Bf[i * OUTD + t] = bf;
    }
}

// ---------------- main fused kernel ----------------
// All SMEM leading dims are ≡ 4 (mod 32) to kill bank conflicts on
// wmma fragment loads (old strides 384/128/64/136/392/72 were ≡0 or 8 mod 32).
static constexpr int LDE  = 132;                  // E: 64 x 128 (pad, 132%32=4)
static constexpr int LDU  = 388;                  // U: 64 x 384 (pad, 388%32=4)
static constexpr int LDV  = 68;                   // V chunk: 64 x 64 (pad, 68%32=4)
static constexpr int LDW0 = 388;                  // panel stride for 384-col panels
static constexpr int LDWF = 132;                  // panel stride for 128-col panels
static constexpr int LDW1 = 68;                   // panel stride for 64-col panels
static constexpr int LDO  = 132;                  // epilogue O stride

static constexpr int OFF_E  = 0;
static constexpr int OFF_U  = OFF_E + TILE * LDE;       // 8448
static constexpr int OFF_V  = OFF_U + TILE * LDU;       // 33280
static constexpr int OFF_W  = OFF_V + TILE * LDV;       // 37632
static constexpr int PANEL_MAX = 32 * LDW0;             // 12416 (biggest: 32x384 panel)
static constexpr int OFF_BA = OFF_W + PANEL_MAX;        // 50048
static constexpr int SMEM_FLOATS = OFF_BA + HID;        // 50432
static constexpr int SMEM_BYTES  = SMEM_FLOATS * 4;     // 201728 B

// load rows x cols panel of W (global row stride rstride) into sW with smem
// leading dim sstride (sstride >= cols, multiple of 4)
__device__ __forceinline__ void load_panel(float* __restrict__ sW,
                                           const float* __restrict__ W,
                                           int k0, int rows, int c0, int cols,
                                           int rstride, int sstride, int tid) {
    int cpr = cols >> 2;
    int total = rows * cpr;
    for (int idx = tid; idx < total; idx += NTHREADS) {
        int r = idx / cpr, c4 = idx - r * cpr;
        float4 x = *(const float4*)(W + (size_t)(k0 + r) * rstride + c0 + (c4 << 2));
        x.x = tf32r(x.x); x.y = tf32r(x.y); x.z = tf32r(x.z); x.w = tf32r(x.w);
        *(float4*)(sW + r * sstride + (c4 << 2)) = x;
    }
}

__global__ __launch_bounds__(NTHREADS, 1)
void k_main(const float* __restrict__ edge,
            const float* __restrict__ w_t0,
            const float* __restrict__ b_t1,
            const float* __restrict__ w_t1,
            const float* __restrict__ w_fin,
            const float* __restrict__ ln_g,
            const float* __restrict__ ln_b,
            float* __restrict__ out) {
    extern __shared__ float sm[];
    float* sE  = sm + OFF_E;
    float* sU  = sm + OFF_U;
    float* sV  = sm + OFF_V;
    float* sW  = sm + OFF_W;
    float* sBA = sm + OFF_BA;

    const int tid  = threadIdx.x;
    const int lane = tid & 31;
    const int wid  = tid >> 5;
    const int wy   = wid & 3;     // M tile (rows wy*16)
    const int wx   = wid >> 2;    // N split

    const int i  = blockIdx.x >> 3;
    const int j0 = (blockIdx.x & 7) * TILE;

    // ---- phase 0: load E tile (tf32-rounded) + A0 row ----
    {
        const float4* src = (const float4*)(edge + (size_t)(i * NN + j0) * EIN);
        for (int v = tid; v < TILE * 32; v += NTHREADS) {
            int r = v >> 5, c4 = v & 31;
            float4 x = src[r * 32 + c4];
            x.x = tf32r(x.x); x.y = tf32r(x.y); x.z = tf32r(x.z); x.w = tf32r(x.w);
            *(float4*)(sE + r * LDE + (c4 << 2)) = x;
        }
        for (int c = tid; c < HID; c += NTHREADS) sBA[c] = g_A0[i * HID + c];
    }

    // ---- GEMM-A: U = relu(E @ W0e + A0[i] + B0[j]) ; M=64 N=384 K=128 ----
    {
        wmma::fragment<wmma::accumulator, 16, 16, 8, float> acc[12];
#pragma unroll
        for (int n = 0; n < 12; n++) wmma::fill_fragment(acc[n], 0.f);
        for (int kc = 0; kc < EIN; kc += 32) {
            __syncthreads();
            load_panel(sW, w_t0, kc, 32, 0, 384, HID, LDW0, tid);
            __syncthreads();
#pragma unroll
            for (int k8 = 0; k8 < 32; k8 += 8) {
                wmma::fragment<wmma::matrix_a, 16, 16, 8, wmma::precision::tf32, wmma::row_major> a;
                wmma::load_matrix_sync(a, sE + wy * 16 * LDE + kc + k8, LDE);
#pragma unroll
                for (int n = 0; n < 12; n++) {
                    wmma::fragment<wmma::matrix_b, 16, 16, 8, wmma::precision::tf32, wmma::row_major> b;
                    wmma::load_matrix_sync(b, sW + k8 * LDW0 + wx * 192 + n * 16, LDW0);
                    wmma::mma_sync(acc[n], a, b, acc[n]);
                }
            }
        }
        __syncthreads();
#pragma unroll
        for (int n = 0; n < 12; n++)
            wmma::store_matrix_sync(sU + wy * 16 * LDU + wx * 192 + n * 16, acc[n], LDU,
                                    wmma::mem_row_major);
        __syncthreads();
        // bias + relu + tf32-round
        for (int v = tid; v < TILE * HID; v += NTHREADS) {
            int r = v / HID, c = v - r * HID;
            float x = sU[r * LDU + c] + sBA[c] + g_B0[(size_t)(j0 + r) * HID + c];
            sU[r * LDU + c] = tf32r(fmaxf(x, 0.f));
        }
    }

    // ---- GEMM-B: O_acc = E @ w_fin[0:128,:] ; M=64 N=128 K=128 (regs persist) ----
    wmma::fragment<wmma::accumulator, 16, 16, 8, float> accO[4];
#pragma unroll
    for (int n = 0; n < 4; n++) wmma::fill_fragment(accO[n], 0.f);
    for (int kc = 0; kc < EIN; kc += 32) {
        __syncthreads();
        load_panel(sW, w_fin, kc, 32, 0, 128, OUTD, LDWF, tid);
        __syncthreads();
#pragma unroll
        for (int k8 = 0; k8 < 32; k8 += 8) {
            wmma::fragment<wmma::matrix_a, 16, 16, 8, wmma::precision::tf32, wmma::row_major> a;
            wmma::load_matrix_sync(a, sE + wy * 16 * LDE + kc + k8, LDE);
#pragma unroll
            for (int n = 0; n < 4; n++) {
                wmma::fragment<wmma::matrix_b, 16, 16, 8, wmma::precision::tf32, wmma::row_major> b;
                wmma::load_matrix_sync(b, sW + k8 * LDWF + wx * 64 + n * 16, LDWF);
                wmma::mma_sync(accO[n], a, b, accO[n]);
            }
        }
    }

    // ---- GEMM-C/D chunked: V = relu(U@W1[:,chunk]+b1); O_acc += V @ w_fin[chunk,:] ----
    for (int vc = 0; vc < 6; vc++) {
        wmma::fragment<wmma::accumulator, 16, 16, 8, float> accV[2];
        wmma::fill_fragment(accV[0], 0.f);
        wmma::fill_fragment(accV[1], 0.f);
        for (int kc = 0; kc < HID; kc += 64) {
            __syncthreads();
            load_panel(sW, w_t1, kc, 64, vc * 64, 64, HID, LDW1, tid);
            __syncthreads();
#pragma unroll
            for (int k8 = 0; k8 < 64; k8 += 8) {
                wmma::fragment<wmma::matrix_a, 16, 16, 8, wmma::precision::tf32, wmma::row_major> a;
                wmma::load_matrix_sync(a, sU + wy * 16 * LDU + kc + k8, LDU);
#pragma unroll
                for (int s = 0; s < 2; s++) {
                    wmma::fragment<wmma::matrix_b, 16, 16, 8, wmma::precision::tf32, wmma::row_major> b;
                    wmma::load_matrix_sync(b, sW + k8 * LDW1 + wx * 32 + s * 16, LDW1);
                    wmma::mma_sync(accV[s], a, b, accV[s]);
                }
            }
        }
        __syncthreads();
#pragma unroll
        for (int s = 0; s < 2; s++)
            wmma::store_matrix_sync(sV + wy * 16 * LDV + wx * 32 + s * 16, accV[s], LDV,
                                    wmma::mem_row_major);
        __syncthreads();
        for (int v = tid; v < TILE * 64; v += NTHREADS) {
            int r = v >> 6, c = v & 63;
            float x = sV[r * LDV + c] + b_t1[vc * 64 + c];
            sV[r * LDV + c] = tf32r(fmaxf(x, 0.f));
        }
        __syncthreads();
        load_panel(sW, w_fin, vc * 64, 64, 0, 128, OUTD, LDWF, tid);
        __syncthreads();
#pragma unroll
        for (int k8 = 0; k8 < 64; k8 += 8) {
            wmma::fragment<wmma::matrix_a, 16, 16, 8, wmma::precision::tf32, wmma::row_major> a;
            wmma::load_matrix_sync(a, sV + wy * 16 * LDV + k8, LDV);
#pragma unroll
            for (int n = 0; n < 4; n++) {
                wmma::fragment<wmma::matrix_b, 16, 16, 8, wmma::precision::tf32, wmma::row_major> b;
                wmma::load_matrix_sync(b, sW + k8 * LDWF + wx * 64 + n * 16, LDWF);
                wmma::mma_sync(accO[n], a, b, accO[n]);
            }
        }
    }

    // ---- epilogue: O + Af[i] + Bf[j], LayerNorm, store ----
    float* sO = sU;  // reuse (64 x LDO)
    __syncthreads();
#pragma unroll
    for (int n = 0; n < 4; n++)
        wmma::store_matrix_sync(sO + wy * 16 * LDO + wx * 64 + n * 16, accO[n], LDO,
                                wmma::mem_row_major);
    __syncthreads();

    for (int rr = 0; rr < 8; rr++) {
        int r = wid * 8 + rr;
        float x[4];
        float sum = 0.f;
#pragma unroll
        for (int q = 0; q < 4; q++) {
            int c = lane + q * 32;
            x[q] = sO[r * LDO + c] + g_Af[i * OUTD + c] + g_Bf[(size_t)(j0 + r) * OUTD + c];
            sum += x[q];
        }
#pragma unroll
        for (int off = 16; off; off >>= 1) sum += __shfl_xor_sync(0xffffffffu, sum, off);
        float mu = sum * (1.f / 128.f);
        float vs = 0.f;
#pragma unroll
        for (int q = 0; q < 4; q++) { float d = x[q] - mu; vs += d * d; }
#pragma unroll
        for (int off = 16; off; off >>= 1) vs += __shfl_xor_sync(0xffffffffu, vs, off);
        float inv = rsqrtf(vs * (1.f / 128.f) + 1e-5f);
        size_t base = (size_t)(i * NN + j0 + r) * OUTD;
#pragma unroll
        for (int q = 0; q < 4; q++) {
            int c = lane + q * 32;
            out[base + c] = (x[q] - mu) * inv * ln_g[c] + ln_b[c];
        }
    }
}

extern "C" void kernel_launch(void* const* d_in, const int* in_sizes, int n_in,
                              void* d_out, int out_size) {
    const float* node   = (const float*)d_in[0];
    const float* edge   = (const float*)d_in[1];
    const float* w_init = (const float*)d_in[2];
    const float* b_init = (const float*)d_in[3];
    const float* w_t0   = (const float*)d_in[4];
    const float* b_t0   = (const float*)d_in[5];
    const float* w_t1   = (const float*)d_in[6];
    const float* b_t1   = (const float*)d_in[7];
    const float* w_fin  = (const float*)d_in[8];
    const float* b_fin  = (const float*)d_in[9];
    const float* ln_g   = (const float*)d_in[10];
    const float* ln_b   = (const float*)d_in[11];
    float* out = (float*)d_out;

    cudaFuncSetAttribute(k_main, cudaFuncAttributeMaxDynamicSharedMemorySize, SMEM_BYTES);

    k_nb<<<NN, 128>>>(node, w_init, b_init);
    k_bias<<<NN, 384>>>(w_t0, b_t0, w_fin, b_fin);
    k_main<<<NN * 8, NTHREADS, SMEM_BYTES>>>(edge, w_t0, b_t1, w_t1, w_fin, ln_g, ln_b, out);
}

// round 6
// speedup vs baseline: 2.5090x; 1.3948x over previous
#include <cuda_runtime.h>
#include <mma.h>
#include <cstdint>

using namespace nvcuda;

#define NN 512
#define NTHREADS 256

// ---- device scratch ----
__device__ float g_A0[NN * 384];
__device__ float g_B0[NN * 384];
__device__ float g_Af[NN * 128];
__device__ float g_Bf[NN * 128];
__device__ __align__(16) float g_Wm[128 * 512];    // merged [w_t0 rows0:128 | w_fin rows0:128], rounded
__device__ __align__(16) float g_w1r[384 * 384];   // w_t1 rounded
__device__ __align__(16) float g_wfr[384 * 128];   // w_fin rounded

__device__ __forceinline__ float tf32r(float x) {
    float y; asm("cvt.rna.tf32.f32 %0, %1;" : "=f"(y) : "f"(x)); return y;
}
__device__ __forceinline__ uint32_t smem_u32(const void* p) {
    uint32_t a;
    asm("{ .reg .u64 t; cvta.to.shared.u64 t, %1; cvt.u32.u64 %0, t; }" : "=r"(a) : "l"(p));
    return a;
}
__device__ __forceinline__ void cpa16(uint32_t s, const float* g) {
    asm volatile("cp.async.cg.shared.global [%0], [%1], 16;" :: "r"(s), "l"(g));
}
#define CP_COMMIT() asm volatile("cp.async.commit_group;" ::: "memory")
#define CP_WAIT()   asm volatile("cp.async.wait_group 0;" ::: "memory")

// ---------------- one fused precompute kernel ----------------
__global__ void k_pre(const float* __restrict__ node, const float* __restrict__ w_init,
                      const float* __restrict__ b_init, const float* __restrict__ w_t0,
                      const float* __restrict__ b_t0, const float* __restrict__ w_t1,
                      const float* __restrict__ w_fin, const float* __restrict__ b_fin) {
    int i = blockIdx.x, t = threadIdx.x;  // 384 threads
    __shared__ float sn[256], snb[128];
    for (int c = t; c < 256; c += 384) sn[c] = node[i * 256 + c];
    __syncthreads();
    if (t < 128) {
        float acc = b_init[t];
#pragma unroll 8
        for (int k = 0; k < 256; k++) acc += sn[k] * w_init[k * 128 + t];
        snb[t] = acc;
    }
    __syncthreads();
    float a = b_t0[t], b2 = 0.f;
#pragma unroll 8
    for (int k = 0; k < 128; k++) {
        float nv = snb[k];
        a  += nv * w_t0[(128 + k) * 384 + t];
        b2 += nv * w_t0[(256 + k) * 384 + t];
    }
    g_A0[i * 384 + t] = a;
    g_B0[i * 384 + t] = b2;
    if (t < 128) {
        float af = b_fin[t], bf = 0.f;
#pragma unroll 8
        for (int k = 0; k < 128; k++) {
            float nv = snb[k];
            af += nv * w_fin[(128 + k) * 128 + t];
            bf += nv * w_fin[(256 + k) * 128 + t];
        }
        g_Af[i * 128 + t] = af;
        g_Bf[i * 128 + t] = bf;
    }
    // weight rounding: 512 elements per block, 262144 total
    for (int x = t; x < 512; x += 384) {
        int idx = i * 512 + x;
        if (idx < 65536) {
            int r = idx >> 9, c = idx & 511;
            g_Wm[idx] = tf32r(c < 384 ? w_t0[r * 384 + c] : w_fin[r * 128 + (c - 384)]);
        } else if (idx < 65536 + 147456) {
            int j = idx - 65536;
            g_w1r[j] = tf32r(w_t1[j]);
        } else {
            int j = idx - 212992;
            g_wfr[j] = tf32r(w_fin[j]);
        }
    }
}

// ---------------- main kernel ----------------
// SMEM (bytes): EO 33792 | U 99328 | V 17408 | slot0 33792 | slot1 33792 | sBA 1536
static constexpr int OFF_EO = 0;       // 64 x 132 (E phase1 / O scratch)
static constexpr int OFF_U  = 33792;   // 64 x 388
static constexpr int OFF_V  = 133120;  // 64 x 68
static constexpr int OFF_S0 = 150528;  // panel slot 0 (8448 floats)
static constexpr int OFF_S1 = 184320;  // panel slot 1
static constexpr int OFF_BA = 218112;  // 384 floats
static constexpr int SMEM_BYTES = 219648;

// panel prefetchers (all threads participate; byte-address slots)
__device__ __forceinline__ void pf_p1(uint32_t s, int c, int tid) {
    const float* base = g_Wm + c * 16 * 512;           // 16 rows x 128 f4, dst stride 516
    for (int x = tid; x < 2048; x += NTHREADS) {
        int r = x >> 7, c4 = x & 127;
        cpa16(s + r * 2064 + c4 * 16, base + r * 512 + c4 * 4);
    }
}
__device__ __forceinline__ void pf_w1(uint32_t s, int vc, int kq, int tid) {
    const float* base = g_w1r + kq * 64 * 384 + vc * 64;  // 64 rows x 16 f4, dst stride 68
    for (int x = tid; x < 1024; x += NTHREADS) {
        int r = x >> 4, c4 = x & 15;
        cpa16(s + r * 272 + c4 * 16, base + r * 384 + c4 * 4);
    }
}
__device__ __forceinline__ void pf_wf(uint32_t s, int vc, int tid) {
    const float* base = g_wfr + vc * 64 * 128;         // 64 rows x 32 f4, dst stride 132
    for (int x = tid; x < 2048; x += NTHREADS) {
        int r = x >> 5, c4 = x & 31;
        cpa16(s + r * 528 + c4 * 16, base + r * 128 + c4 * 4);
    }
}

__global__ __launch_bounds__(NTHREADS, 1)
void k_main(const float* __restrict__ edge, const float* __restrict__ b_t1,
            const float* __restrict__ ln_g, const float* __restrict__ ln_b,
            float* __restrict__ out) {
    extern __shared__ __align__(16) char smem[];
    float* sEO = (float*)(smem + OFF_EO);
    float* sU  = (float*)(smem + OFF_U);
    float* sV  = (float*)(smem + OFF_V);
    float* sBA = (float*)(smem + OFF_BA);
    const uint32_t sb = smem_u32(smem);
    const uint32_t slotA[2] = { sb + OFF_S0, sb + OFF_S1 };
    float* const slotP[2] = { (float*)(smem + OFF_S0), (float*)(smem + OFF_S1) };

    const int tid = threadIdx.x, lane = tid & 31, wid = tid >> 5;
    const int wy = wid & 3, wx = wid >> 2;
    const int i = blockIdx.x >> 3, j0 = (blockIdx.x & 7) * 64;

    // prefetch phase-1 chunk 0 immediately (issue index 0)
    pf_p1(slotA[0], 0, tid);
    CP_COMMIT();

    // load E tile (tf32-rounded, stride 132) + A0 row
    {
        const float4* src = (const float4*)(edge + (size_t)(i * NN + j0) * 128);
        for (int v = tid; v < 64 * 32; v += NTHREADS) {
            int r = v >> 5, c4 = v & 31;
            float4 x = src[(size_t)r * 32 + c4];
            x.x = tf32r(x.x); x.y = tf32r(x.y); x.z = tf32r(x.z); x.w = tf32r(x.w);
            *(float4*)(sEO + r * 132 + c4 * 4) = x;
        }
        for (int c = tid; c < 384; c += NTHREADS) sBA[c] = g_A0[i * 384 + c];
    }

    // ---- phase 1: [U | O] = E @ [W0e | WfE]; M=64 N=512 K=128 ----
    // per warp: all 64 M-rows, 64 N-cols (cols wid*64..)
    wmma::fragment<wmma::accumulator, 16, 16, 8, float> acc[16];
#pragma unroll
    for (int q = 0; q < 16; q++) wmma::fill_fragment(acc[q], 0.f);

    for (int c = 0; c < 8; c++) {
        CP_WAIT(); __syncthreads();
        if (c < 7) pf_p1(slotA[(c + 1) & 1], c + 1, tid);
        else       pf_w1(slotA[0], 0, 0, tid);          // issue idx 8 -> slot 0
        CP_COMMIT();
        float* sw = slotP[c & 1];
#pragma unroll
        for (int k8 = 0; k8 < 16; k8 += 8) {
            wmma::fragment<wmma::matrix_a, 16, 16, 8, wmma::precision::tf32, wmma::row_major> af[4];
#pragma unroll
            for (int m = 0; m < 4; m++)
                wmma::load_matrix_sync(af[m], sEO + m * 16 * 132 + c * 16 + k8, 132);
            wmma::fragment<wmma::matrix_b, 16, 16, 8, wmma::precision::tf32, wmma::row_major> bf[4];
#pragma unroll
            for (int n = 0; n < 4; n++)
                wmma::load_matrix_sync(bf[n], sw + k8 * 516 + wid * 64 + n * 16, 516);
#pragma unroll
            for (int m = 0; m < 4; m++)
#pragma unroll
                for (int n = 0; n < 4; n++)
                    wmma::mma_sync(acc[m * 4 + n], af[m], bf[n], acc[m * 4 + n]);
        }
    }

    // ---- extract: U cols (wid<6) -> sU; O cols (wid>=6) -> sEO (raw) ----
    __syncthreads();   // all mma done before overwriting sEO (aliased with E)
#pragma unroll
    for (int m = 0; m < 4; m++)
#pragma unroll
        for (int n = 0; n < 4; n++) {
            if (wid < 6)
                wmma::store_matrix_sync(sU + m * 16 * 388 + wid * 64 + n * 16, acc[m * 4 + n], 388,
                                        wmma::mem_row_major);
            else
                wmma::store_matrix_sync(sEO + m * 16 * 132 + (wid - 6) * 64 + n * 16, acc[m * 4 + n], 132,
                                        wmma::mem_row_major);
        }
    __syncthreads();

    // relu pass on U (bias + relu + tf32 round)
    for (int v = tid; v < 64 * 96; v += NTHREADS) {
        int r = v / 96, c4 = v - r * 96;
        float4 x  = *(float4*)(sU + r * 388 + c4 * 4);
        float4 ba = *(const float4*)(sBA + c4 * 4);
        float4 b0 = *(const float4*)(g_B0 + (size_t)(j0 + r) * 384 + c4 * 4);
        x.x = tf32r(fmaxf(x.x + ba.x + b0.x, 0.f));
        x.y = tf32r(fmaxf(x.y + ba.y + b0.y, 0.f));
        x.z = tf32r(fmaxf(x.z + ba.z + b0.z, 0.f));
        x.w = tf32r(fmaxf(x.w + ba.w + b0.w, 0.f));
        *(float4*)(sU + r * 388 + c4 * 4) = x;
    }

    // load persistent O accumulators (layout 4M x 2N(64))
    wmma::fragment<wmma::accumulator, 16, 16, 8, float> accO[4];
#pragma unroll
    for (int n = 0; n < 4; n++)
        wmma::load_matrix_sync(accO[n], sEO + wy * 16 * 132 + wx * 64 + n * 16, 132,
                               wmma::mem_row_major);
    __syncthreads();   // sU ready for all warps

    // ---- phase 2: per vc: V = relu(U @ W1c + b1); O += V @ Wf[vc] ----
    for (int vc = 0; vc < 6; vc++) {
        wmma::fragment<wmma::accumulator, 16, 16, 8, float> accV[2];
        wmma::fill_fragment(accV[0], 0.f);
        wmma::fill_fragment(accV[1], 0.f);
        for (int kq = 0; kq < 6; kq++) {
            CP_WAIT(); __syncthreads();
            int up = 8 + vc * 7 + kq;                    // use index -> slot parity
            if (kq < 5) pf_w1(slotA[(up + 1) & 1], vc, kq + 1, tid);
            else        pf_wf(slotA[(up + 1) & 1], vc, tid);
            CP_COMMIT();
            float* sw = slotP[up & 1];
#pragma unroll
            for (int k8 = 0; k8 < 8; k8++) {
                wmma::fragment<wmma::matrix_a, 16, 16, 8, wmma::precision::tf32, wmma::row_major> a;
                wmma::load_matrix_sync(a, sU + wy * 16 * 388 + kq * 64 + k8 * 8, 388);
#pragma unroll
                for (int s = 0; s < 2; s++) {
                    wmma::fragment<wmma::matrix_b, 16, 16, 8, wmma::precision::tf32, wmma::row_major> b;
                    wmma::load_matrix_sync(b, sw + k8 * 8 * 68 + wx * 32 + s * 16, 68);
                    wmma::mma_sync(accV[s], a, b, accV[s]);
                }
            }
        }
        CP_WAIT(); __syncthreads();                      // Wf ready
        int upf = 8 + vc * 7 + 6;
        float* swf = slotP[upf & 1];
        // V extract
#pragma unroll
        for (int s = 0; s < 2; s++)
            wmma::store_matrix_sync(sV + wy * 16 * 68 + wx * 32 + s * 16, accV[s], 68,
                                    wmma::mem_row_major);
        __syncthreads();
        for (int v = tid; v < 64 * 64; v += NTHREADS) {
            int r = v >> 6, c = v & 63;
            float x = sV[r * 68 + c] + b_t1[vc * 64 + c];
            sV[r * 68 + c] = tf32r(fmaxf(x, 0.f));
        }
        if (vc < 5) { pf_w1(slotA[(upf + 1) & 1], vc + 1, 0, tid); CP_COMMIT(); }
        __syncthreads();                                 // sV ready
        // O update: M=64 N=128 K=64
#pragma unroll
        for (int k8 = 0; k8 < 8; k8++) {
            wmma::fragment<wmma::matrix_a, 16, 16, 8, wmma::precision::tf32, wmma::row_major> a;
            wmma::load_matrix_sync(a, sV + wy * 16 * 68 + k8 * 8, 68);
#pragma unroll
            for (int n = 0; n < 4; n++) {
                wmma::fragment<wmma::matrix_b, 16, 16, 8, wmma::precision::tf32, wmma::row_major> b;
                wmma::load_matrix_sync(b, swf + k8 * 8 * 132 + wx * 64 + n * 16, 132);
                wmma::mma_sync(accO[n], a, b, accO[n]);
            }
        }
    }

    // ---- epilogue: O + Af + Bf, LayerNorm, store ----
    __syncthreads();
#pragma unroll
    for (int n = 0; n < 4; n++)
        wmma::store_matrix_sync(sEO + wy * 16 * 132 + wx * 64 + n * 16, accO[n], 132,
                                wmma::mem_row_major);
    __syncthreads();

    for (int rr = 0; rr < 8; rr++) {
        int r = wid * 8 + rr;
        float x[4];
        float sum = 0.f;
#pragma unroll
        for (int q = 0; q < 4; q++) {
            int c = lane + q * 32;
            x[q] = sEO[r * 132 + c] + g_Af[i * 128 + c] + g_Bf[(size_t)(j0 + r) * 128 + c];
            sum += x[q];
        }
#pragma unroll
        for (int off = 16; off; off >>= 1) sum += __shfl_xor_sync(0xffffffffu, sum, off);
        float mu = sum * (1.f / 128.f);
        float vs = 0.f;
#pragma unroll
        for (int q = 0; q < 4; q++) { float d = x[q] - mu; vs += d * d; }
#pragma unroll
        for (int off = 16; off; off >>= 1) vs += __shfl_xor_sync(0xffffffffu, vs, off);
        float inv = rsqrtf(vs * (1.f / 128.f) + 1e-5f);
        size_t base = (size_t)(i * NN + j0 + r) * 128;
#pragma unroll
        for (int q = 0; q < 4; q++) {
            int c = lane + q * 32;
            out[base + c] = (x[q] - mu) * inv * ln_g[c] + ln_b[c];
        }
    }
}

extern "C" void kernel_launch(void* const* d_in, const int* in_sizes, int n_in,
                              void* d_out, int out_size) {
    const float* node   = (const float*)d_in[0];
    const float* edge   = (const float*)d_in[1];
    const float* w_init = (const float*)d_in[2];
    const float* b_init = (const float*)d_in[3];
    const float* w_t0   = (const float*)d_in[4];
    const float* b_t0   = (const float*)d_in[5];
    const float* w_t1   = (const float*)d_in[6];
    const float* b_t1   = (const float*)d_in[7];
    const float* w_fin  = (const float*)d_in[8];
    const float* b_fin  = (const float*)d_in[9];
    const float* ln_g   = (const float*)d_in[10];
    const float* ln_b   = (const float*)d_in[11];
    float* out = (float*)d_out;

    cudaFuncSetAttribute(k_main, cudaFuncAttributeMaxDynamicSharedMemorySize, SMEM_BYTES);

    k_pre<<<NN, 384>>>(node, w_init, b_init, w_t0, b_t0, w_t1, w_fin, b_fin);
    k_main<<<NN * 8, NTHREADS, SMEM_BYTES>>>(edge, b_t1, ln_g, ln_b, out);
}

// round 7
// speedup vs baseline: 2.6177x; 1.0433x over previous
#include <cuda_runtime.h>
#include <mma.h>
#include <cstdint>

using namespace nvcuda;

#define NN 512
#define NTHREADS 512

// ---- device scratch ----
__device__ float g_A0[NN * 384];
__device__ float g_B0[NN * 384];
__device__ float g_Af[NN * 128];
__device__ float g_Bf[NN * 128];
__device__ __align__(16) float g_Wm[128 * 512];    // merged [w_t0 rows0:128 | w_fin rows0:128], rounded
__device__ __align__(16) float g_w1r[384 * 384];   // w_t1 rounded
__device__ __align__(16) float g_wfr[384 * 128];   // w_fin rounded

__device__ __forceinline__ float tf32r(float x) {
    float y; asm("cvt.rna.tf32.f32 %0, %1;" : "=f"(y) : "f"(x)); return y;
}
__device__ __forceinline__ uint32_t smem_u32(const void* p) {
    uint32_t a;
    asm("{ .reg .u64 t; cvta.to.shared.u64 t, %1; cvt.u32.u64 %0, t; }" : "=r"(a) : "l"(p));
    return a;
}
__device__ __forceinline__ void cpa16(uint32_t s, const float* g) {
    asm volatile("cp.async.cg.shared.global [%0], [%1], 16;" :: "r"(s), "l"(g));
}
#define CP_COMMIT() asm volatile("cp.async.commit_group;" ::: "memory")
#define CP_WAIT()   asm volatile("cp.async.wait_group 0;" ::: "memory")

// ---------------- one fused precompute kernel ----------------
__global__ void k_pre(const float* __restrict__ node, const float* __restrict__ w_init,
                      const float* __restrict__ b_init, const float* __restrict__ w_t0,
                      const float* __restrict__ b_t0, const float* __restrict__ w_t1,
                      const float* __restrict__ w_fin, const float* __restrict__ b_fin) {
    int i = blockIdx.x, t = threadIdx.x;  // 384 threads
    __shared__ float sn[256], snb[128];
    for (int c = t; c < 256; c += 384) sn[c] = node[i * 256 + c];
    __syncthreads();
    if (t < 128) {
        float acc = b_init[t];
#pragma unroll 8
        for (int k = 0; k < 256; k++) acc += sn[k] * w_init[k * 128 + t];
        snb[t] = acc;
    }
    __syncthreads();
    float a = b_t0[t], b2 = 0.f;
#pragma unroll 8
    for (int k = 0; k < 128; k++) {
        float nv = snb[k];
        a  += nv * w_t0[(128 + k) * 384 + t];
        b2 += nv * w_t0[(256 + k) * 384 + t];
    }
    g_A0[i * 384 + t] = a;
    g_B0[i * 384 + t] = b2;
    if (t < 128) {
        float af = b_fin[t], bf = 0.f;
#pragma unroll 8
        for (int k = 0; k < 128; k++) {
            float nv = snb[k];
            af += nv * w_fin[(128 + k) * 128 + t];
            bf += nv * w_fin[(256 + k) * 128 + t];
        }
        g_Af[i * 128 + t] = af;
        g_Bf[i * 128 + t] = bf;
    }
    for (int x = t; x < 512; x += 384) {
        int idx = i * 512 + x;
        if (idx < 65536) {
            int r = idx >> 9, c = idx & 511;
            g_Wm[idx] = tf32r(c < 384 ? w_t0[r * 384 + c] : w_fin[r * 128 + (c - 384)]);
        } else if (idx < 65536 + 147456) {
            int j = idx - 65536;
            g_w1r[j] = tf32r(w_t1[j]);
        } else {
            int j = idx - 212992;
            g_wfr[j] = tf32r(w_fin[j]);
        }
    }
}

// ---------------- main kernel ----------------
// SMEM: EO 33792 (E / O scratch / V scratch) | U 99328 | slot0 33792 | slot1 33792 | BA 1536
static constexpr int OFF_EO = 0;       // 64 x 132
static constexpr int OFF_U  = 33792;   // 64 x 388
static constexpr int OFF_S0 = 133120;  // panel slot 0
static constexpr int OFF_S1 = 166912;  // panel slot 1
static constexpr int OFF_BA = 200704;  // 384 floats
static constexpr int SMEM_BYTES = 202240;

// panel prefetchers
__device__ __forceinline__ void pf_p1(uint32_t s, int c, int tid) {
    const float* base = g_Wm + c * 16 * 512;              // 16 rows x 128 f4, dst stride 516
    for (int x = tid; x < 2048; x += NTHREADS) {
        int r = x >> 7, c4 = x & 127;
        cpa16(s + r * 2064 + c4 * 16, base + r * 512 + c4 * 4);
    }
}
__device__ __forceinline__ void pf_w1b(uint32_t s, int vc2, int kq, int tid) {
    const float* base = g_w1r + kq * 64 * 384 + vc2 * 128; // 64 rows x 32 f4, dst stride 132
    for (int x = tid; x < 2048; x += NTHREADS) {
        int r = x >> 5, c4 = x & 31;
        cpa16(s + r * 528 + c4 * 16, base + r * 384 + c4 * 4);
    }
}
__device__ __forceinline__ void pf_wf(uint32_t s, int h, int tid) {
    const float* base = g_wfr + h * 64 * 128;              // 64 rows x 32 f4, dst stride 132
    for (int x = tid; x < 2048; x += NTHREADS) {
        int r = x >> 5, c4 = x & 31;
        cpa16(s + r * 528 + c4 * 16, base + r * 128 + c4 * 4);
    }
}

__global__ __launch_bounds__(NTHREADS, 1)
void k_main(const float* __restrict__ edge, const float* __restrict__ b_t1,
            const float* __restrict__ ln_g, const float* __restrict__ ln_b,
            float* __restrict__ out) {
    extern __shared__ __align__(16) char smem[];
    float* sEO = (float*)(smem + OFF_EO);
    float* sU  = (float*)(smem + OFF_U);
    float* sBA = (float*)(smem + OFF_BA);
    const uint32_t sb = smem_u32(smem);
    const uint32_t slotA[2] = { sb + OFF_S0, sb + OFF_S1 };
    float* const slotP[2] = { (float*)(smem + OFF_S0), (float*)(smem + OFF_S1) };

    const int tid = threadIdx.x, lane = tid & 31, wid = tid >> 5;   // 16 warps
    const int wy = wid & 3, wx = wid >> 2;                          // phase-2 tiling 4x4
    const int i = blockIdx.x >> 3, j0 = (blockIdx.x & 7) * 64;

    pf_p1(slotA[0], 0, tid);
    CP_COMMIT();

    // load E tile (tf32-rounded, stride 132) + A0 row
    {
        const float4* src = (const float4*)(edge + (size_t)(i * NN + j0) * 128);
        for (int v = tid; v < 64 * 32; v += NTHREADS) {
            int r = v >> 5, c4 = v & 31;
            float4 x = src[(size_t)r * 32 + c4];
            x.x = tf32r(x.x); x.y = tf32r(x.y); x.z = tf32r(x.z); x.w = tf32r(x.w);
            *(float4*)(sEO + r * 132 + c4 * 4) = x;
        }
        for (int c = tid; c < 384; c += NTHREADS) sBA[c] = g_A0[i * 384 + c];
    }

    // ---- phase 1: [U | O] = E @ [W0e | WfE]; M=64 N=512 K=128 ----
    // per warp: all 64 M-rows, 32 N-cols (cols wid*32..)
    wmma::fragment<wmma::accumulator, 16, 16, 8, float> acc[8];    // [m0..3][n0..1]
#pragma unroll
    for (int q = 0; q < 8; q++) wmma::fill_fragment(acc[q], 0.f);

    for (int c = 0; c < 8; c++) {
        CP_WAIT(); __syncthreads();
        if (c < 7) pf_p1(slotA[(c + 1) & 1], c + 1, tid);
        else       pf_w1b(slotA[0], 0, 0, tid);          // issue idx 8 -> slot 0
        CP_COMMIT();
        float* sw = slotP[c & 1];
#pragma unroll
        for (int k8 = 0; k8 < 16; k8 += 8) {
            wmma::fragment<wmma::matrix_a, 16, 16, 8, wmma::precision::tf32, wmma::row_major> af[4];
#pragma unroll
            for (int m = 0; m < 4; m++)
                wmma::load_matrix_sync(af[m], sEO + m * 16 * 132 + c * 16 + k8, 132);
            wmma::fragment<wmma::matrix_b, 16, 16, 8, wmma::precision::tf32, wmma::row_major> bf[2];
#pragma unroll
            for (int n = 0; n < 2; n++)
                wmma::load_matrix_sync(bf[n], sw + k8 * 516 + wid * 32 + n * 16, 516);
#pragma unroll
            for (int m = 0; m < 4; m++)
#pragma unroll
                for (int n = 0; n < 2; n++)
                    wmma::mma_sync(acc[m * 2 + n], af[m], bf[n], acc[m * 2 + n]);
        }
    }

    // ---- extract: U cols (wid<12) -> sU; O cols (wid>=12) -> sEO (raw) ----
    __syncthreads();
#pragma unroll
    for (int m = 0; m < 4; m++)
#pragma unroll
        for (int n = 0; n < 2; n++) {
            if (wid < 12)
                wmma::store_matrix_sync(sU + m * 16 * 388 + wid * 32 + n * 16, acc[m * 2 + n], 388,
                                        wmma::mem_row_major);
            else
                wmma::store_matrix_sync(sEO + m * 16 * 132 + (wid - 12) * 32 + n * 16, acc[m * 2 + n], 132,
                                        wmma::mem_row_major);
        }
    __syncthreads();

    // relu pass on U (bias + relu + tf32 round)
    for (int v = tid; v < 64 * 96; v += NTHREADS) {
        int r = v / 96, c4 = v - r * 96;
        float4 x  = *(float4*)(sU + r * 388 + c4 * 4);
        float4 ba = *(const float4*)(sBA + c4 * 4);
        float4 b0 = *(const float4*)(g_B0 + (size_t)(j0 + r) * 384 + c4 * 4);
        x.x = tf32r(fmaxf(x.x + ba.x + b0.x, 0.f));
        x.y = tf32r(fmaxf(x.y + ba.y + b0.y, 0.f));
        x.z = tf32r(fmaxf(x.z + ba.z + b0.z, 0.f));
        x.w = tf32r(fmaxf(x.w + ba.w + b0.w, 0.f));
        *(float4*)(sU + r * 388 + c4 * 4) = x;
    }

    // persistent O accumulators: warp tile 16x32 (rows wy*16, cols wx*32)
    wmma::fragment<wmma::accumulator, 16, 16, 8, float> accO[2];
#pragma unroll
    for (int n = 0; n < 2; n++)
        wmma::load_matrix_sync(accO[n], sEO + wy * 16 * 132 + wx * 32 + n * 16, 132,
                               wmma::mem_row_major);
    __syncthreads();   // sU relu done; sEO free for V scratch

    float* sV = sEO;   // V scratch 64 x 128 (stride 132) aliases EO
    int up = 8;

    // ---- phase 2: 3 iters, each: V(64x128) = relu(U @ W1[:,vc2*128..]); O += V @ Wf ----
    for (int vc2 = 0; vc2 < 3; vc2++) {
        wmma::fragment<wmma::accumulator, 16, 16, 8, float> accV[2];
        wmma::fill_fragment(accV[0], 0.f);
        wmma::fill_fragment(accV[1], 0.f);
        for (int kq = 0; kq < 6; kq++) {
            CP_WAIT(); __syncthreads();
            if (kq < 5) pf_w1b(slotA[(up + 1) & 1], vc2, kq + 1, tid);
            else        pf_wf(slotA[(up + 1) & 1], vc2 * 2, tid);
            CP_COMMIT();
            float* sw = slotP[up & 1];
#pragma unroll
            for (int k8 = 0; k8 < 8; k8++) {
                wmma::fragment<wmma::matrix_a, 16, 16, 8, wmma::precision::tf32, wmma::row_major> a;
                wmma::load_matrix_sync(a, sU + wy * 16 * 388 + kq * 64 + k8 * 8, 388);
#pragma unroll
                for (int n = 0; n < 2; n++) {
                    wmma::fragment<wmma::matrix_b, 16, 16, 8, wmma::precision::tf32, wmma::row_major> b;
                    wmma::load_matrix_sync(b, sw + k8 * 8 * 132 + wx * 32 + n * 16, 132);
                    wmma::mma_sync(accV[n], a, b, accV[n]);
                }
            }
            up++;
        }
        // Wf half 0 ready; prefetch half 1
        CP_WAIT(); __syncthreads();
        pf_wf(slotA[(up + 1) & 1], vc2 * 2 + 1, tid);
        CP_COMMIT();
        float* swf0 = slotP[up & 1];
        up++;
        // V extract + bias + relu + round
#pragma unroll
        for (int n = 0; n < 2; n++)
            wmma::store_matrix_sync(sV + wy * 16 * 132 + wx * 32 + n * 16, accV[n], 132,
                                    wmma::mem_row_major);
        __syncthreads();
        for (int v = tid; v < 64 * 32; v += NTHREADS) {
            int r = v >> 5, c4 = v & 31;
            float4 x  = *(float4*)(sV + r * 132 + c4 * 4);
            float4 bb = *(const float4*)(b_t1 + vc2 * 128 + c4 * 4);
            x.x = tf32r(fmaxf(x.x + bb.x, 0.f));
            x.y = tf32r(fmaxf(x.y + bb.y, 0.f));
            x.z = tf32r(fmaxf(x.z + bb.z, 0.f));
            x.w = tf32r(fmaxf(x.w + bb.w, 0.f));
            *(float4*)(sV + r * 132 + c4 * 4) = x;
        }
        __syncthreads();
        // O update part 0: K = V cols 0..64
#pragma unroll
        for (int k8 = 0; k8 < 8; k8++) {
            wmma::fragment<wmma::matrix_a, 16, 16, 8, wmma::precision::tf32, wmma::row_major> a;
            wmma::load_matrix_sync(a, sV + wy * 16 * 132 + k8 * 8, 132);
#pragma unroll
            for (int n = 0; n < 2; n++) {
                wmma::fragment<wmma::matrix_b, 16, 16, 8, wmma::precision::tf32, wmma::row_major> b;
                wmma::load_matrix_sync(b, swf0 + k8 * 8 * 132 + wx * 32 + n * 16, 132);
                wmma::mma_sync(accO[n], a, b, accO[n]);
            }
        }
        // Wf half 1 ready; prefetch next W1 panel
        CP_WAIT(); __syncthreads();
        float* swf1 = slotP[up & 1];
        if (vc2 < 2) { pf_w1b(slotA[(up + 1) & 1], vc2 + 1, 0, tid); CP_COMMIT(); }
        up++;
        // O update part 1: K = V cols 64..128
#pragma unroll
        for (int k8 = 0; k8 < 8; k8++) {
            wmma::fragment<wmma::matrix_a, 16, 16, 8, wmma::precision::tf32, wmma::row_major> a;
            wmma::load_matrix_sync(a, sV + wy * 16 * 132 + 64 + k8 * 8, 132);
#pragma unroll
            for (int n = 0; n < 2; n++) {
                wmma::fragment<wmma::matrix_b, 16, 16, 8, wmma::precision::tf32, wmma::row_major> b;
                wmma::load_matrix_sync(b, swf1 + k8 * 8 * 132 + wx * 32 + n * 16, 132);
                wmma::mma_sync(accO[n], a, b, accO[n]);
            }
        }
    }

    // ---- epilogue ----
    __syncthreads();
#pragma unroll
    for (int n = 0; n < 2; n++)
        wmma::store_matrix_sync(sEO + wy * 16 * 132 + wx * 32 + n * 16, accO[n], 132,
                                wmma::mem_row_major);
    __syncthreads();

    for (int rr = 0; rr < 4; rr++) {
        int r = wid * 4 + rr;
        float x[4];
        float sum = 0.f;
#pragma unroll
        for (int q = 0; q < 4; q++) {
            int c = lane + q * 32;
            x[q] = sEO[r * 132 + c] + g_Af[i * 128 + c] + g_Bf[(size_t)(j0 + r) * 128 + c];
            sum += x[q];
        }
#pragma unroll
        for (int off = 16; off; off >>= 1) sum += __shfl_xor_sync(0xffffffffu, sum, off);
        float mu = sum * (1.f / 128.f);
        float vs = 0.f;
#pragma unroll
        for (int q = 0; q < 4; q++) { float d = x[q] - mu; vs += d * d; }
#pragma unroll
        for (int off = 16; off; off >>= 1) vs += __shfl_xor_sync(0xffffffffu, vs, off);
        float inv = rsqrtf(vs * (1.f / 128.f) + 1e-5f);
        size_t base = (size_t)(i * NN + j0 + r) * 128;
#pragma unroll
        for (int q = 0; q < 4; q++) {
            int c = lane + q * 32;
            out[base + c] = (x[q] - mu) * inv * ln_g[c] + ln_b[c];
        }
    }
}

extern "C" void kernel_launch(void* const* d_in, const int* in_sizes, int n_in,
                              void* d_out, int out_size) {
    const float* node   = (const float*)d_in[0];
    const float* edge   = (const float*)d_in[1];
    const float* w_init = (const float*)d_in[2];
    const float* b_init = (const float*)d_in[3];
    const float* w_t0   = (const float*)d_in[4];
    const float* b_t0   = (const float*)d_in[5];
    const float* w_t1   = (const float*)d_in[6];
    const float* b_t1   = (const float*)d_in[7];
    const float* w_fin  = (const float*)d_in[8];
    const float* b_fin  = (const float*)d_in[9];
    const float* ln_g   = (const float*)d_in[10];
    const float* ln_b   = (const float*)d_in[11];
    float* out = (float*)d_out;

    cudaFuncSetAttribute(k_main, cudaFuncAttributeMaxDynamicSharedMemorySize, SMEM_BYTES);

    k_pre<<<NN, 384>>>(node, w_init, b_init, w_t0, b_t0, w_t1, w_fin, b_fin);
    k_main<<<NN * 8, NTHREADS, SMEM_BYTES>>>(edge, b_t1, ln_g, ln_b, out);
}

// round 10
// speedup vs baseline: 6.9093x; 2.6394x over previous
#include <cuda_runtime.h>
#include <cuda_fp16.h>
#include <mma.h>
#include <cstdint>

using namespace nvcuda;

#define NN 512
#define NTHREADS 512

// ---- device scratch ----
__device__ float g_A0[NN * 384];
__device__ float g_B0[NN * 384];
__device__ float g_Af[NN * 128];
__device__ float g_Bf[NN * 128];
__device__ __align__(16) __half g_Wmh[128 * 512];   // merged [w_t0 rows0:128 | w_fin rows0:128]
__device__ __align__(16) __half g_w1rh[384 * 384];  // w_t1 half
__device__ __align__(16) __half g_wfrh[384 * 128];  // w_fin half

__device__ __forceinline__ uint32_t smem_u32(const void* p) {
    uint32_t a;
    asm("{ .reg .u64 t; cvta.to.shared.u64 t, %1; cvt.u32.u64 %0, t; }" : "=r"(a) : "l"(p));
    return a;
}
__device__ __forceinline__ void cpa16(uint32_t s, const void* g) {
    asm volatile("cp.async.cg.shared.global [%0], [%1], 16;" :: "r"(s), "l"(g));
}
#define CP_COMMIT() asm volatile("cp.async.commit_group;" ::: "memory")
#define CP_WAIT()   asm volatile("cp.async.wait_group 0;" ::: "memory")

// ---------------- fused precompute ----------------
__global__ void k_pre(const float* __restrict__ node, const float* __restrict__ w_init,
                      const float* __restrict__ b_init, const float* __restrict__ w_t0,
                      const float* __restrict__ b_t0, const float* __restrict__ w_t1,
                      const float* __restrict__ w_fin, const float* __restrict__ b_fin) {
    int i = blockIdx.x, t = threadIdx.x;  // 384 threads
    __shared__ float sn[256], snb[128];
    for (int c = t; c < 256; c += 384) sn[c] = node[i * 256 + c];
    __syncthreads();
    if (t < 128) {
        float acc = b_init[t];
#pragma unroll 8
        for (int k = 0; k < 256; k++) acc += sn[k] * w_init[k * 128 + t];
        snb[t] = acc;
    }
    __syncthreads();
    float a = b_t0[t], b2 = 0.f;
#pragma unroll 8
    for (int k = 0; k < 128; k++) {
        float nv = snb[k];
        a  += nv * w_t0[(128 + k) * 384 + t];
        b2 += nv * w_t0[(256 + k) * 384 + t];
    }
    g_A0[i * 384 + t] = a;
    g_B0[i * 384 + t] = b2;
    if (t < 128) {
        float af = b_fin[t], bf = 0.f;
#pragma unroll 8
        for (int k = 0; k < 128; k++) {
            float nv = snb[k];
            af += nv * w_fin[(128 + k) * 128 + t];
            bf += nv * w_fin[(256 + k) * 128 + t];
        }
        g_Af[i * 128 + t] = af;
        g_Bf[i * 128 + t] = bf;
    }
    for (int x = t; x < 512; x += 384) {
        int idx = i * 512 + x;
        if (idx < 65536) {
            int r = idx >> 9, c = idx & 511;
            g_Wmh[idx] = __float2half_rn(c < 384 ? w_t0[r * 384 + c] : w_fin[r * 128 + (c - 384)]);
        } else if (idx < 65536 + 147456) {
            int j = idx - 65536;
            g_w1rh[j] = __float2half_rn(w_t1[j]);
        } else {
            int j = idx - 212992;
            g_wfrh[j] = __float2half_rn(w_fin[j]);
        }
    }
}

// ---------------- main kernel ----------------
// SMEM (bytes). Slots are 33280 B: the phase-1 panel is 32 rows x 520 halves
// = 33280 B (R8 sized them 32768 -> overflow + race into the other slot).
static constexpr int OFF_E  = 0;        // E half 64x136 (17408); V scratch aliases after phase 1
static constexpr int OFF_O  = 17408;    // O fp32 64x132 (33792)
static constexpr int OFF_U  = 51200;    // U half 64x392 (50176)
static constexpr int OFF_S0 = 101376;   // panel slot 0 (33280)
static constexpr int OFF_S1 = 134656;   // panel slot 1 (33280)
static constexpr int OFF_ST = 167936;   // per-warp staging 16 x (16x20 fp32) (20480)
static constexpr int OFF_BA = 188416;   // A0 row, 384 fp32 (1536)
static constexpr int SMEM_BYTES = 189952;

// phase-1 panel: K-chunk c -> rows 32c..32c+32 of g_Wmh (512 cols), smem stride 520 halves
__device__ __forceinline__ void pf_p1(uint32_t s, int c, int tid) {
    const __half* base = g_Wmh + c * 32 * 512;
    for (int x = tid; x < 2048; x += NTHREADS) {
        int r = x >> 6, c16 = x & 63;
        cpa16(s + r * 1040 + c16 * 16, base + r * 512 + c16 * 8);
    }
}
// phase-2 W1 panel: rows kq*64..+64, cols vc2*128..+128, smem stride 136 halves
__device__ __forceinline__ void pf_w1b(uint32_t s, int vc2, int kq, int tid) {
    const __half* base = g_w1rh + kq * 64 * 384 + vc2 * 128;
    for (int x = tid; x < 1024; x += NTHREADS) {
        int r = x >> 4, c = x & 15;
        cpa16(s + r * 272 + c * 16, base + r * 384 + c * 8);
    }
}
// Wf panel: rows h*64..+64 (128 cols), smem stride 136 halves
__device__ __forceinline__ void pf_wf(uint32_t s, int h, int tid) {
    const __half* base = g_wfrh + h * 64 * 128;
    for (int x = tid; x < 1024; x += NTHREADS) {
        int r = x >> 4, c = x & 15;
        cpa16(s + r * 272 + c * 16, base + r * 128 + c * 8);
    }
}

typedef wmma::fragment<wmma::matrix_a, 16, 16, 16, __half, wmma::row_major> FragA;
typedef wmma::fragment<wmma::matrix_b, 16, 16, 16, __half, wmma::row_major> FragB;
typedef wmma::fragment<wmma::accumulator, 16, 16, 16, float> FragC;

__global__ __launch_bounds__(NTHREADS, 1)
void k_main(const float* __restrict__ edge, const float* __restrict__ b_t1,
            const float* __restrict__ ln_g, const float* __restrict__ ln_b,
            float* __restrict__ out) {
    extern __shared__ __align__(16) char smem[];
    __half* sE  = (__half*)(smem + OFF_E);     // stride 136
    float*  sO  = (float*) (smem + OFF_O);     // stride 132
    __half* sU  = (__half*)(smem + OFF_U);     // stride 392
    float*  sST = (float*) (smem + OFF_ST);
    float*  sBA = (float*) (smem + OFF_BA);
    const uint32_t sb = smem_u32(smem);
    const uint32_t slotA[2] = { sb + OFF_S0, sb + OFF_S1 };
    __half* const slotP[2] = { (__half*)(smem + OFF_S0), (__half*)(smem + OFF_S1) };

    const int tid = threadIdx.x, lane = tid & 31, wid = tid >> 5;   // 16 warps
    const int wy = wid & 3, wx = wid >> 2;
    const int i = blockIdx.x >> 3, j0 = (blockIdx.x & 7) * 64;
    float* stg = sST + wid * 320;   // 16 x 20 fp32 private staging

    pf_p1(slotA[0], 0, tid);
    CP_COMMIT();

    // load E tile -> fp16 (stride 136) + A0 row
    {
        const float4* src = (const float4*)(edge + (size_t)(i * NN + j0) * 128);
        for (int v = tid; v < 64 * 16; v += NTHREADS) {
            int r = v >> 4, c8 = v & 15;
            float4 x0 = src[(size_t)r * 32 + c8 * 2];
            float4 x1 = src[(size_t)r * 32 + c8 * 2 + 1];
            __half2* d = (__half2*)(sE + r * 136 + c8 * 8);
            d[0] = __floats2half2_rn(x0.x, x0.y);
            d[1] = __floats2half2_rn(x0.z, x0.w);
            d[2] = __floats2half2_rn(x1.x, x1.y);
            d[3] = __floats2half2_rn(x1.z, x1.w);
        }
        for (int c = tid; c < 384; c += NTHREADS) sBA[c] = g_A0[i * 384 + c];
    }

    // ---- phase 1: [U | O] = E @ [W0e | WfE]; M=64 N=512 K=128, 4 chunks of K=32 ----
    FragC acc[8];   // [m0..3][n0..1], warp cols wid*32..
#pragma unroll
    for (int q = 0; q < 8; q++) wmma::fill_fragment(acc[q], 0.f);

    for (int c = 0; c < 4; c++) {
        CP_WAIT(); __syncthreads();
        if (c < 3) pf_p1(slotA[(c + 1) & 1], c + 1, tid);
        else       pf_w1b(slotA[0], 0, 0, tid);
        CP_COMMIT();
        __half* sw = slotP[c & 1];
#pragma unroll
        for (int k16 = 0; k16 < 2; k16++) {
            FragA af[4];
#pragma unroll
            for (int m = 0; m < 4; m++)
                wmma::load_matrix_sync(af[m], sE + m * 16 * 136 + c * 32 + k16 * 16, 136);
            FragB bf[2];
#pragma unroll
            for (int n = 0; n < 2; n++)
                wmma::load_matrix_sync(bf[n], sw + k16 * 16 * 520 + wid * 32 + n * 16, 520);
#pragma unroll
            for (int m = 0; m < 4; m++)
#pragma unroll
                for (int n = 0; n < 2; n++)
                    wmma::mma_sync(acc[m * 2 + n], af[m], bf[n], acc[m * 2 + n]);
        }
    }

    // ---- extract ----
    if (wid < 12) {
#pragma unroll
        for (int m = 0; m < 4; m++)
#pragma unroll
            for (int n = 0; n < 2; n++) {
                wmma::store_matrix_sync(stg, acc[m * 2 + n], 20, wmma::mem_row_major);
                __syncwarp();
                int r = m * 16 + (lane >> 1);
                int cg = wid * 32 + n * 16 + (lane & 1) * 8;
                const float* b0 = g_B0 + (size_t)(j0 + r) * 384 + cg;
                const float* st = stg + (lane >> 1) * 20 + (lane & 1) * 8;
                __half2* d = (__half2*)(sU + r * 392 + cg);
#pragma unroll
                for (int q = 0; q < 4; q++) {
                    float v0 = st[q * 2]     + sBA[cg + q * 2]     + b0[q * 2];
                    float v1 = st[q * 2 + 1] + sBA[cg + q * 2 + 1] + b0[q * 2 + 1];
                    d[q] = __floats2half2_rn(fmaxf(v0, 0.f), fmaxf(v1, 0.f));
                }
                __syncwarp();
            }
    } else {
#pragma unroll
        for (int m = 0; m < 4; m++)
#pragma unroll
            for (int n = 0; n < 2; n++)
                wmma::store_matrix_sync(sO + m * 16 * 132 + (wid - 12) * 32 + n * 16,
                                        acc[m * 2 + n], 132, wmma::mem_row_major);
    }
    __syncthreads();

    // persistent O accumulators: warp tile rows wy*16, cols wx*32
    FragC accO[2];
#pragma unroll
    for (int n = 0; n < 2; n++)
        wmma::load_matrix_sync(accO[n], sO + wy * 16 * 132 + wx * 32 + n * 16, 132,
                               wmma::mem_row_major);
    __syncthreads();

    __half* sV = sE;   // V scratch 64x128 half (stride 136), aliases dead E
    int up = 4;

    // ---- phase 2: 3 iters: V(64x128) = relu(U @ W1[:,vc2*128..] + b1); O += V @ Wf ----
    for (int vc2 = 0; vc2 < 3; vc2++) {
        FragC accV[2];
        wmma::fill_fragment(accV[0], 0.f);
        wmma::fill_fragment(accV[1], 0.f);
        for (int kq = 0; kq < 6; kq++) {
            CP_WAIT(); __syncthreads();
            if (kq < 5) pf_w1b(slotA[(up + 1) & 1], vc2, kq + 1, tid);
            else        pf_wf(slotA[(up + 1) & 1], vc2 * 2, tid);
            CP_COMMIT();
            __half* sw = slotP[up & 1];
#pragma unroll
            for (int k16 = 0; k16 < 4; k16++) {
                FragA a;
                wmma::load_matrix_sync(a, sU + wy * 16 * 392 + kq * 64 + k16 * 16, 392);
#pragma unroll
                for (int n = 0; n < 2; n++) {
                    FragB b;
                    wmma::load_matrix_sync(b, sw + k16 * 16 * 136 + wx * 32 + n * 16, 136);
                    wmma::mma_sync(accV[n], a, b, accV[n]);
                }
            }
            up++;
        }
        // Wf half 0 ready; prefetch half 1
        CP_WAIT(); __syncthreads();
        pf_wf(slotA[(up + 1) & 1], vc2 * 2 + 1, tid);
        CP_COMMIT();
        __half* swf0 = slotP[up & 1];
        up++;
        // V extract: bias + relu -> fp16 sV (private staging)
#pragma unroll
        for (int n = 0; n < 2; n++) {
            wmma::store_matrix_sync(stg, accV[n], 20, wmma::mem_row_major);
            __syncwarp();
            int r = wy * 16 + (lane >> 1);
            int cl = wx * 32 + n * 16 + (lane & 1) * 8;
            const float* bt = b_t1 + vc2 * 128 + cl;
            const float* st = stg + (lane >> 1) * 20 + (lane & 1) * 8;
            __half2* d = (__half2*)(sV + r * 136 + cl);
#pragma unroll
            for (int q = 0; q < 4; q++) {
                float v0 = st[q * 2]     + bt[q * 2];
                float v1 = st[q * 2 + 1] + bt[q * 2 + 1];
                d[q] = __floats2half2_rn(fmaxf(v0, 0.f), fmaxf(v1, 0.f));
            }
            __syncwarp();
        }
        __syncthreads();
        // O += V[:,0:64] @ Wf(h0)
#pragma unroll
        for (int k16 = 0; k16 < 4; k16++) {
            FragA a;
            wmma::load_matrix_sync(a, sV + wy * 16 * 136 + k16 * 16, 136);
#pragma unroll
            for (int n = 0; n < 2; n++) {
                FragB b;
                wmma::load_matrix_sync(b, swf0 + k16 * 16 * 136 + wx * 32 + n * 16, 136);
                wmma::mma_sync(accO[n], a, b, accO[n]);
            }
        }
        // Wf half 1 ready; prefetch next W1 panel
        CP_WAIT(); __syncthreads();
        __half* swf1 = slotP[up & 1];
        if (vc2 < 2) { pf_w1b(slotA[(up + 1) & 1], vc2 + 1, 0, tid); CP_COMMIT(); }
        up++;
        // O += V[:,64:128] @ Wf(h1)
#pragma unroll
        for (int k16 = 0; k16 < 4; k16++) {
            FragA a;
            wmma::load_matrix_sync(a, sV + wy * 16 * 136 + 64 + k16 * 16, 136);
#pragma unroll
            for (int n = 0; n < 2; n++) {
                FragB b;
                wmma::load_matrix_sync(b, swf1 + k16 * 16 * 136 + wx * 32 + n * 16, 136);
                wmma::mma_sync(accO[n], a, b, accO[n]);
            }
        }
    }

    // ---- epilogue: O + Af + Bf, LayerNorm, store ----
    __syncthreads();
#pragma unroll
    for (int n = 0; n < 2; n++)
        wmma::store_matrix_sync(sO + wy * 16 * 132 + wx * 32 + n * 16, accO[n], 132,
                                wmma::mem_row_major);
    __syncthreads();

    for (int rr = 0; rr < 4; rr++) {
        int r = wid * 4 + rr;
        float x[4];
        float sum = 0.f;
#pragma unroll
        for (int q = 0; q < 4; q++) {
            int c = lane + q * 32;
            x[q] = sO[r * 132 + c] + g_Af[i * 128 + c] + g_Bf[(size_t)(j0 + r) * 128 + c];
            sum += x[q];
        }
#pragma unroll
        for (int off = 16; off; off >>= 1) sum += __shfl_xor_sync(0xffffffffu, sum, off);
        float mu = sum * (1.f / 128.f);
        float vs = 0.f;
#pragma unroll
        for (int q = 0; q < 4; q++) { float d = x[q] - mu; vs += d * d; }
#pragma unroll
        for (int off = 16; off; off >>= 1) vs += __shfl_xor_sync(0xffffffffu, vs, off);
        float inv = rsqrtf(vs * (1.f / 128.f) + 1e-5f);
        size_t base = (size_t)(i * NN + j0 + r) * 128;
#pragma unroll
        for (int q = 0; q < 4; q++) {
            int c = lane + q * 32;
            out[base + c] = (x[q] - mu) * inv * ln_g[c] + ln_b[c];
        }
    }
}

extern "C" void kernel_launch(void* const* d_in, const int* in_sizes, int n_in,
                              void* d_out, int out_size) {
    const float* node   = (const float*)d_in[0];
    const float* edge   = (const float*)d_in[1];
    const float* w_init = (const float*)d_in[2];
    const float* b_init = (const float*)d_in[3];
    const float* w_t0   = (const float*)d_in[4];
    const float* b_t0   = (const float*)d_in[5];
    const float* w_t1   = (const float*)d_in[6];
    const float* b_t1   = (const float*)d_in[7];
    const float* w_fin  = (const float*)d_in[8];
    const float* b_fin  = (const float*)d_in[9];
    const float* ln_g   = (const float*)d_in[10];
    const float* ln_b   = (const float*)d_in[11];
    float* out = (float*)d_out;

    cudaFuncSetAttribute(k_main, cudaFuncAttributeMaxDynamicSharedMemorySize, SMEM_BYTES);

    k_pre<<<NN, 384>>>(node, w_init, b_init, w_t0, b_t0, w_t1, w_fin, b_fin);
    k_main<<<NN * 8, NTHREADS, SMEM_BYTES>>>(edge, b_t1, ln_g, ln_b, out);
}

// round 11
// speedup vs baseline: 7.0328x; 1.0179x over previous
#include <cuda_runtime.h>
#include <cuda_fp16.h>
#include <mma.h>
#include <cstdint>

using namespace nvcuda;

#define NN 512
#define NTHREADS 256

// ---- device scratch ----
__device__ float g_A0[NN * 384];
__device__ float g_B0[NN * 384];
__device__ float g_Af[NN * 128];
__device__ float g_Bf[NN * 128];
__device__ __align__(16) __half g_Wmh[128 * 512];   // merged [w_t0 rows0:128 | w_fin rows0:128]
__device__ __align__(16) __half g_w1rh[384 * 384];  // w_t1 half
__device__ __align__(16) __half g_wfrh[384 * 128];  // w_fin half

__device__ __forceinline__ uint32_t smem_u32(const void* p) {
    uint32_t a;
    asm("{ .reg .u64 t; cvta.to.shared.u64 t, %1; cvt.u32.u64 %0, t; }" : "=r"(a) : "l"(p));
    return a;
}
__device__ __forceinline__ void cpa16(uint32_t s, const void* g) {
    asm volatile("cp.async.cg.shared.global [%0], [%1], 16;" :: "r"(s), "l"(g));
}
#define CP_COMMIT() asm volatile("cp.async.commit_group;" ::: "memory")
#define CP_WAIT()   asm volatile("cp.async.wait_group 0;" ::: "memory")

// ---------------- fused precompute (unchanged from R10) ----------------
__global__ void k_pre(const float* __restrict__ node, const float* __restrict__ w_init,
                      const float* __restrict__ b_init, const float* __restrict__ w_t0,
                      const float* __restrict__ b_t0, const float* __restrict__ w_t1,
                      const float* __restrict__ w_fin, const float* __restrict__ b_fin) {
    int i = blockIdx.x, t = threadIdx.x;  // 384 threads
    __shared__ float sn[256], snb[128];
    for (int c = t; c < 256; c += 384) sn[c] = node[i * 256 + c];
    __syncthreads();
    if (t < 128) {
        float acc = b_init[t];
#pragma unroll 8
        for (int k = 0; k < 256; k++) acc += sn[k] * w_init[k * 128 + t];
        snb[t] = acc;
    }
    __syncthreads();
    float a = b_t0[t], b2 = 0.f;
#pragma unroll 8
    for (int k = 0; k < 128; k++) {
        float nv = snb[k];
        a  += nv * w_t0[(128 + k) * 384 + t];
        b2 += nv * w_t0[(256 + k) * 384 + t];
    }
    g_A0[i * 384 + t] = a;
    g_B0[i * 384 + t] = b2;
    if (t < 128) {
        float af = b_fin[t], bf = 0.f;
#pragma unroll 8
        for (int k = 0; k < 128; k++) {
            float nv = snb[k];
            af += nv * w_fin[(128 + k) * 128 + t];
            bf += nv * w_fin[(256 + k) * 128 + t];
        }
        g_Af[i * 128 + t] = af;
        g_Bf[i * 128 + t] = bf;
    }
    for (int x = t; x < 512; x += 384) {
        int idx = i * 512 + x;
        if (idx < 65536) {
            int r = idx >> 9, c = idx & 511;
            g_Wmh[idx] = __float2half_rn(c < 384 ? w_t0[r * 384 + c] : w_fin[r * 128 + (c - 384)]);
        } else if (idx < 65536 + 147456) {
            int j = idx - 65536;
            g_w1rh[j] = __float2half_rn(w_t1[j]);
        } else {
            int j = idx - 212992;
            g_wfrh[j] = __float2half_rn(w_fin[j]);
        }
    }
}

// ---------------- main kernel ----------------
// 256 threads (8 warps), fat warp tiles. SMEM (bytes):
static constexpr int OFF_V  = 0;        // V half 64x392 (50176); E (64x136) aliases head
static constexpr int OFF_U  = 50176;    // U half 64x392 (50176)
static constexpr int OFF_O  = 100352;   // O fp32 64x132 (33792)
static constexpr int OFF_S0 = 134144;   // panel slot 0 (33280)
static constexpr int OFF_S1 = 167424;   // panel slot 1 (33280)
static constexpr int OFF_ST = 200704;   // per-warp staging 8 x (16x20 fp32) (10240)
static constexpr int OFF_BA = 210944;   // A0 row, 384 fp32 (1536)
static constexpr int SMEM_BYTES = 212480;

// phase-1 panel: K-chunk c -> rows 32c..+32 of g_Wmh (512 cols), smem stride 520 halves
__device__ __forceinline__ void pf_p1(uint32_t s, int c, int tid) {
    const __half* base = g_Wmh + c * 32 * 512;
    for (int x = tid; x < 2048; x += NTHREADS) {
        int r = x >> 6, c16 = x & 63;
        cpa16(s + r * 1040 + c16 * 16, base + r * 512 + c16 * 8);
    }
}
// W1 panel: K-rows k*32..+32, FULL 384 cols, smem stride 392 halves
__device__ __forceinline__ void pf_w1(uint32_t s, int k, int tid) {
    const __half* base = g_w1rh + k * 32 * 384;
    for (int x = tid; x < 1536; x += NTHREADS) {
        int r = x >> 5, c = x & 31;            // 32 rows x 48 c16... (x>>5 gives 48 rows?) no:
        // 1536 = 32 rows * 48 c16
        r = x / 48; c = x - r * 48;
        cpa16(s + r * 784 + c * 16, base + r * 384 + c * 8);
    }
}
// Wf panel: K-rows h*96..+96 (128 cols), smem stride 136 halves
__device__ __forceinline__ void pf_wf(uint32_t s, int h, int tid) {
    const __half* base = g_wfrh + h * 96 * 128;
    for (int x = tid; x < 1536; x += NTHREADS) {
        int r = x >> 4, c = x & 15;
        cpa16(s + r * 272 + c * 16, base + r * 128 + c * 8);
    }
}

typedef wmma::fragment<wmma::matrix_a, 16, 16, 16, __half, wmma::row_major> FragA;
typedef wmma::fragment<wmma::matrix_b, 16, 16, 16, __half, wmma::row_major> FragB;
typedef wmma::fragment<wmma::accumulator, 16, 16, 16, float> FragC;

__global__ __launch_bounds__(NTHREADS, 1)
void k_main(const float* __restrict__ edge, const float* __restrict__ b_t1,
            const float* __restrict__ ln_g, const float* __restrict__ ln_b,
            float* __restrict__ out) {
    extern __shared__ __align__(16) char smem[];
    __half* sE  = (__half*)(smem + OFF_V);     // E stride 136 (dies after phase 1)
    __half* sV  = (__half*)(smem + OFF_V);     // V stride 392 (after phase 1)
    __half* sU  = (__half*)(smem + OFF_U);     // stride 392
    float*  sO  = (float*) (smem + OFF_O);     // stride 132
    float*  sST = (float*) (smem + OFF_ST);
    float*  sBA = (float*) (smem + OFF_BA);
    const uint32_t sb = smem_u32(smem);
    const uint32_t slotA[2] = { sb + OFF_S0, sb + OFF_S1 };
    __half* const slotP[2] = { (__half*)(smem + OFF_S0), (__half*)(smem + OFF_S1) };

    const int tid = threadIdx.x, lane = tid & 31, wid = tid >> 5;   // 8 warps
    const int i = blockIdx.x >> 3, j0 = (blockIdx.x & 7) * 64;
    float* stg = sST + wid * 320;   // 16x20 fp32 private staging

    pf_p1(slotA[0], 0, tid);
    CP_COMMIT();

    // load E tile -> fp16 (stride 136) + A0 row
    {
        const float4* src = (const float4*)(edge + (size_t)(i * NN + j0) * 128);
        for (int v = tid; v < 64 * 16; v += NTHREADS) {
            int r = v >> 4, c8 = v & 15;
            float4 x0 = src[(size_t)r * 32 + c8 * 2];
            float4 x1 = src[(size_t)r * 32 + c8 * 2 + 1];
            __half2* d = (__half2*)(sE + r * 136 + c8 * 8);
            d[0] = __floats2half2_rn(x0.x, x0.y);
            d[1] = __floats2half2_rn(x0.z, x0.w);
            d[2] = __floats2half2_rn(x1.x, x1.y);
            d[3] = __floats2half2_rn(x1.z, x1.w);
        }
        for (int c = tid; c < 384; c += NTHREADS) sBA[c] = g_A0[i * 384 + c];
    }

    // ---- phase 1: [U | O] = E @ [W0e | WfE]; M=64 N=512 K=128 ----
    // warp tile 64 x 64 (cols wid*64..): 8 loads / 16 mmas
    {
        FragC acc[16];   // [m0..3][n0..3]
#pragma unroll
        for (int q = 0; q < 16; q++) wmma::fill_fragment(acc[q], 0.f);

        for (int c = 0; c < 4; c++) {
            CP_WAIT(); __syncthreads();
            if (c < 3) pf_p1(slotA[(c + 1) & 1], c + 1, tid);
            else       pf_w1(slotA[0], 0, tid);          // use idx 4 -> slot 0
            CP_COMMIT();
            __half* sw = slotP[c & 1];
#pragma unroll
            for (int k16 = 0; k16 < 2; k16++) {
                FragA af[4];
#pragma unroll
                for (int m = 0; m < 4; m++)
                    wmma::load_matrix_sync(af[m], sE + m * 16 * 136 + c * 32 + k16 * 16, 136);
#pragma unroll
                for (int n = 0; n < 4; n++) {
                    FragB bf;
                    wmma::load_matrix_sync(bf, sw + k16 * 16 * 520 + wid * 64 + n * 16, 520);
#pragma unroll
                    for (int m = 0; m < 4; m++)
                        wmma::mma_sync(acc[m * 4 + n], af[m], bf, acc[m * 4 + n]);
                }
            }
        }

        // extract: warps 0-5: U cols wid*64..+64 (bias+relu->fp16 sU);
        //          warps 6-7: O cols (wid-6)*64 raw fp32 -> sO
        if (wid < 6) {
#pragma unroll
            for (int m = 0; m < 4; m++)
#pragma unroll
                for (int n = 0; n < 4; n++) {
                    wmma::store_matrix_sync(stg, acc[m * 4 + n], 20, wmma::mem_row_major);
                    __syncwarp();
                    int r = m * 16 + (lane >> 1);
                    int cg = wid * 64 + n * 16 + (lane & 1) * 8;
                    const float* b0 = g_B0 + (size_t)(j0 + r) * 384 + cg;
                    const float* st = stg + (lane >> 1) * 20 + (lane & 1) * 8;
                    __half2* d = (__half2*)(sU + r * 392 + cg);
#pragma unroll
                    for (int q = 0; q < 4; q++) {
                        float v0 = st[q * 2]     + sBA[cg + q * 2]     + b0[q * 2];
                        float v1 = st[q * 2 + 1] + sBA[cg + q * 2 + 1] + b0[q * 2 + 1];
                        d[q] = __floats2half2_rn(fmaxf(v0, 0.f), fmaxf(v1, 0.f));
                    }
                    __syncwarp();
                }
        } else {
#pragma unroll
            for (int m = 0; m < 4; m++)
#pragma unroll
                for (int n = 0; n < 4; n++)
                    wmma::store_matrix_sync(sO + m * 16 * 132 + (wid - 6) * 64 + n * 16,
                                            acc[m * 4 + n], 132, wmma::mem_row_major);
        }
    }
    // NOTE: E (head of sV region) is dead from here; sU/sO reads are ordered
    // by the sync at the top of the first V-loop iteration.

    // ---- phase 2a: V = relu(U @ W1 + b1); M=64 N=384 K=384, warp tile 64x48 ----
    {
        FragC accV[12];   // [m0..3][n0..2], cols wid*48..
#pragma unroll
        for (int q = 0; q < 12; q++) wmma::fill_fragment(accV[q], 0.f);

        for (int k = 0; k < 12; k++) {
            CP_WAIT(); __syncthreads();
            int u = 4 + k;
            if (k < 11) pf_w1(slotA[(u + 1) & 1], k + 1, tid);
            else        pf_wf(slotA[0], 0, tid);         // use idx 16 -> slot 0
            CP_COMMIT();
            __half* sw = slotP[u & 1];
#pragma unroll
            for (int kk = 0; kk < 2; kk++) {
                FragA af[4];
#pragma unroll
                for (int m = 0; m < 4; m++)
                    wmma::load_matrix_sync(af[m], sU + m * 16 * 392 + k * 32 + kk * 16, 392);
#pragma unroll
                for (int n = 0; n < 3; n++) {
                    FragB bf;
                    wmma::load_matrix_sync(bf, sw + kk * 16 * 392 + wid * 48 + n * 16, 392);
#pragma unroll
                    for (int m = 0; m < 4; m++)
                        wmma::mma_sync(accV[m * 3 + n], af[m], bf, accV[m * 3 + n]);
                }
            }
        }

        // V extract: bias + relu -> fp16 sV (stride 392), cols wid*48..+48
#pragma unroll
        for (int m = 0; m < 4; m++)
#pragma unroll
            for (int n = 0; n < 3; n++) {
                wmma::store_matrix_sync(stg, accV[m * 3 + n], 20, wmma::mem_row_major);
                __syncwarp();
                int r = m * 16 + (lane >> 1);
                int cl = wid * 48 + n * 16 + (lane & 1) * 8;
                const float* bt = b_t1 + cl;
                const float* st = stg + (lane >> 1) * 20 + (lane & 1) * 8;
                __half2* d = (__half2*)(sV + r * 392 + cl);
#pragma unroll
                for (int q = 0; q < 4; q++) {
                    float v0 = st[q * 2]     + bt[q * 2];
                    float v1 = st[q * 2 + 1] + bt[q * 2 + 1];
                    d[q] = __floats2half2_rn(fmaxf(v0, 0.f), fmaxf(v1, 0.f));
                }
                __syncwarp();
            }
    }

    // ---- phase 2b: O += V @ Wf; M=64 N=128 K=384, warp tile 16x64 ----
    {
        const int my = wid & 3, nx = wid >> 2;   // rows my*16, cols nx*64
        FragC accO[4];
#pragma unroll
        for (int n = 0; n < 4; n++)
            wmma::load_matrix_sync(accO[n], sO + my * 16 * 132 + nx * 64 + n * 16, 132,
                                   wmma::mem_row_major);

        for (int h = 0; h < 4; h++) {
            CP_WAIT(); __syncthreads();          // also orders sV writes before reads (h=0)
            int u = 16 + h;
            if (h < 3) pf_wf(slotA[(u + 1) & 1], h + 1, tid);
            CP_COMMIT();
            __half* swf = slotP[u & 1];
#pragma unroll
            for (int kk = 0; kk < 6; kk++) {
                FragA a;
                wmma::load_matrix_sync(a, sV + my * 16 * 392 + h * 96 + kk * 16, 392);
#pragma unroll
                for (int n = 0; n < 4; n++) {
                    FragB b;
                    wmma::load_matrix_sync(b, swf + kk * 16 * 136 + nx * 64 + n * 16, 136);
                    wmma::mma_sync(accO[n], a, b, accO[n]);
                }
            }
        }

        __syncthreads();
#pragma unroll
        for (int n = 0; n < 4; n++)
            wmma::store_matrix_sync(sO + my * 16 * 132 + nx * 64 + n * 16, accO[n], 132,
                                    wmma::mem_row_major);
    }
    __syncthreads();

    // ---- epilogue: O + Af + Bf, LayerNorm, store (8 rows per warp) ----
    for (int rr = 0; rr < 8; rr++) {
        int r = wid * 8 + rr;
        float x[4];
        float sum = 0.f;
#pragma unroll
        for (int q = 0; q < 4; q++) {
            int c = lane + q * 32;
            x[q] = sO[r * 132 + c] + g_Af[i * 128 + c] + g_Bf[(size_t)(j0 + r) * 128 + c];
            sum += x[q];
        }
#pragma unroll
        for (int off = 16; off; off >>= 1) sum += __shfl_xor_sync(0xffffffffu, sum, off);
        float mu = sum * (1.f / 128.f);
        float vs = 0.f;
#pragma unroll
        for (int q = 0; q < 4; q++) { float d = x[q] - mu; vs += d * d; }
#pragma unroll
        for (int off = 16; off; off >>= 1) vs += __shfl_xor_sync(0xffffffffu, vs, off);
        float inv = rsqrtf(vs * (1.f / 128.f) + 1e-5f);
        size_t base = (size_t)(i * NN + j0 + r) * 128;
#pragma unroll
        for (int q = 0; q < 4; q++) {
            int c = lane + q * 32;
            out[base + c] = (x[q] - mu) * inv * ln_g[c] + ln_b[c];
        }
    }
}

extern "C" void kernel_launch(void* const* d_in, const int* in_sizes, int n_in,
                              void* d_out, int out_size) {
    const float* node   = (const float*)d_in[0];
    const float* edge   = (const float*)d_in[1];
    const float* w_init = (const float*)d_in[2];
    const float* b_init = (const float*)d_in[3];
    const float* w_t0   = (const float*)d_in[4];
    const float* b_t0   = (const float*)d_in[5];
    const float* w_t1   = (const float*)d_in[6];
    const float* b_t1   = (const float*)d_in[7];
    const float* w_fin  = (const float*)d_in[8];
    const float* b_fin  = (const float*)d_in[9];
    const float* ln_g   = (const float*)d_in[10];
    const float* ln_b   = (const float*)d_in[11];
    float* out = (float*)d_out;

    cudaFuncSetAttribute(k_main, cudaFuncAttributeMaxDynamicSharedMemorySize, SMEM_BYTES);

    k_pre<<<NN, 384>>>(node, w_init, b_init, w_t0, b_t0, w_t1, w_fin, b_fin);
    k_main<<<NN * 8, NTHREADS, SMEM_BYTES>>>(edge, b_t1, ln_g, ln_b, out);
}